// round 7
// baseline (speedup 1.0000x reference)
#include <cuda_runtime.h>

#define BB 32
#define SS 128
#define KN 12
#define KC 10
#define KT 22
#define DD 200
#define D4 50
#define CC 45
#define CP 48
#define CP4 12
#define FF 1000
#define NTOK 4096

#define NCHUNK 4
#define CHTOK (NTOK / NCHUNK)              // 1024 tokens per chunk (8 batch rows)
#define FEATB_CH (CHTOK / 2)               // 512 feat blocks per chunk

#define GT2 16                             // tokens per gemm tile
#define AR  (GT2 + 4)                      // 20 staged A rows (halo 2 each side)
#define APAD 51                            // shA pitch in float4
#define GEMMB_CH (CHTOK / GT2)             // 64 gemm blocks per chunk

#define TR_ELEMS (FF * CP)                 // 48000
#define TR_BLOCKS ((TR_ELEMS + 255) / 256) // 188

__device__ float g_feat[NTOK * DD];        // [tok, D]
__device__ float g_Wt[FF * CP];            // [k, 48] transposed+padded

// ---------------------------------------------------------------------------
// W transpose: [45,1000] -> [1000,48] (coalesced read along k)
// ---------------------------------------------------------------------------
__global__ void transpose_kernel(const float* __restrict__ W) {
    int idx = blockIdx.x * 256 + threadIdx.x;
    if (idx < TR_ELEMS) {
        int c = idx / FF;
        int k = idx - c * FF;
        g_Wt[k * CP + c] = (c < CC) ? W[c * FF + k] : 0.0f;
    }
}

// ---------------------------------------------------------------------------
// Feat chunk: masked gather+mean, 2 tokens/block (R4-proven version).
// ---------------------------------------------------------------------------
__global__ void __launch_bounds__(128, 16)
feat_kernel(const int* __restrict__ ngram_ids,
            const int* __restrict__ ngram_mask,
            const int* __restrict__ ctx_ids,
            const int* __restrict__ ctx_mask,
            const float* __restrict__ embed,
            int tok0) {
    const int half = threadIdx.x >> 6;
    const int lane = threadIdx.x & 63;
    const int tok  = tok0 + blockIdx.x * 2 + half;

    __shared__ int s_act[2][24];
    __shared__ int s_cnt[2];

    if (lane < 32) {
        int m = 0, id = 0;
        if (lane < KN) {
            id = ngram_ids[tok * KN + lane];
            m  = ngram_mask[tok * KN + lane];
        } else if (lane < KT) {
            id = ctx_ids[tok * KC + lane - KN];
            m  = ctx_mask[tok * KC + lane - KN];
        }
        unsigned bal = __ballot_sync(0xffffffffu, m != 0);
        if (m) s_act[half][__popc(bal & ((1u << lane) - 1u))] = id;
        if (lane == 0) s_cnt[half] = __popc(bal);
    }
    __syncthreads();

    if (lane >= D4) return;

    const int n = s_cnt[half];
    const int* act = s_act[half];
    const float4* e4 = (const float4*)embed;

    float ax = 0.f, ay = 0.f, az = 0.f, aw = 0.f;
    int j = 0;
    for (; j + 4 <= n; j += 4) {
        float4 a = e4[(long long)act[j + 0] * D4 + lane];
        float4 b = e4[(long long)act[j + 1] * D4 + lane];
        float4 c = e4[(long long)act[j + 2] * D4 + lane];
        float4 d = e4[(long long)act[j + 3] * D4 + lane];
        ax += (a.x + b.x) + (c.x + d.x);
        ay += (a.y + b.y) + (c.y + d.y);
        az += (a.z + b.z) + (c.z + d.z);
        aw += (a.w + b.w) + (c.w + d.w);
    }
    for (; j < n; j++) {
        float4 a = e4[(long long)act[j] * D4 + lane];
        ax += a.x; ay += a.y; az += a.z; aw += a.w;
    }

    float inv = 1.0f / (float)(n > 0 ? n : 1);
    float4 r; r.x = ax * inv; r.y = ay * inv; r.z = az * inv; r.w = aw * inv;
    ((float4*)g_feat)[tok * D4 + lane] = r;
}

// ---------------------------------------------------------------------------
// Gemm chunk: window-fused tile.  Block = 16 tokens x 48 c, 192 threads.
// A (20 rows incl halo) staged ONCE; loop w=0..4 accumulating; B chunk per
// (w,h) staged float4-coalesced from g_Wt; writes out + bias directly.
// ---------------------------------------------------------------------------
__global__ void __launch_bounds__(192)
gemm_kernel(const float* __restrict__ bias,
            float* __restrict__ out,
            int tile0) {
    __shared__ float4 shA[AR * APAD];        // 16320 B
    __shared__ float4 shB[100 * CP4];        // 19200 B

    const int tile = tile0 + blockIdx.x;
    const int tokBase = tile * GT2;
    const int b  = tokBase / SS;
    const int s0 = tokBase % SS;

    const int tid = threadIdx.x;
    const int tg = tid & 15;
    const int cg = tid >> 4;                 // 0..11

    const float4* gf4 = (const float4*)g_feat;
    for (int i = tid; i < AR * D4; i += 192) {
        int r  = i / D4;
        int dv = i - r * D4;
        int s  = s0 - 2 + r;
        float4 v = make_float4(0.f, 0.f, 0.f, 0.f);
        if (s >= 0 && s < SS) v = gf4[(b * SS + s) * D4 + dv];
        shA[r * APAD + dv] = v;
    }

    float acc0 = 0.f, acc1 = 0.f, acc2 = 0.f, acc3 = 0.f;
    const float4* Wt4 = (const float4*)g_Wt;

    #pragma unroll
    for (int w = 0; w < 5; w++) {
        #pragma unroll
        for (int h = 0; h < 2; h++) {
            __syncthreads();
            for (int i = tid; i < 100 * CP4; i += 192)
                shB[i] = Wt4[(w * DD + h * 100) * CP4 + i];
            __syncthreads();

            const float4* aRow = &shA[(tg + w) * APAD + h * 25];
            #pragma unroll
            for (int dq = 0; dq < 25; dq++) {
                float4 a  = aRow[dq];
                float4 b0 = shB[(dq * 4 + 0) * CP4 + cg];
                float4 b1 = shB[(dq * 4 + 1) * CP4 + cg];
                float4 b2 = shB[(dq * 4 + 2) * CP4 + cg];
                float4 b3 = shB[(dq * 4 + 3) * CP4 + cg];
                acc0 = fmaf(a.x, b0.x, acc0); acc1 = fmaf(a.x, b0.y, acc1);
                acc2 = fmaf(a.x, b0.z, acc2); acc3 = fmaf(a.x, b0.w, acc3);
                acc0 = fmaf(a.y, b1.x, acc0); acc1 = fmaf(a.y, b1.y, acc1);
                acc2 = fmaf(a.y, b1.z, acc2); acc3 = fmaf(a.y, b1.w, acc3);
                acc0 = fmaf(a.z, b2.x, acc0); acc1 = fmaf(a.z, b2.y, acc1);
                acc2 = fmaf(a.z, b2.z, acc2); acc3 = fmaf(a.z, b2.w, acc3);
                acc0 = fmaf(a.w, b3.x, acc0); acc1 = fmaf(a.w, b3.y, acc1);
                acc2 = fmaf(a.w, b3.z, acc2); acc3 = fmaf(a.w, b3.w, acc3);
            }
        }
    }

    const int c0 = cg * 4;
    float* o = out + (long long)(tokBase + tg) * CC;
    o[c0] = acc0 + bias[c0];
    if (c0 + 1 < CC) o[c0 + 1] = acc1 + bias[c0 + 1];
    if (c0 + 2 < CC) o[c0 + 2] = acc2 + bias[c0 + 2];
    if (c0 + 3 < CC) o[c0 + 3] = acc3 + bias[c0 + 3];
}

// ---------------------------------------------------------------------------
// Pipelined launch: feat chunks on the capture stream; transpose + gemm
// chunks on a forked stream gated by events. Hardware deps, no spinning.
// ---------------------------------------------------------------------------
extern "C" void kernel_launch(void* const* d_in, const int* in_sizes, int n_in,
                              void* d_out, int out_size) {
    const int*   ngram_ids  = (const int*)d_in[0];
    const int*   ngram_mask = (const int*)d_in[1];
    const int*   ctx_ids    = (const int*)d_in[2];
    const int*   ctx_mask   = (const int*)d_in[3];
    const float* embed      = (const float*)d_in[4];
    const float* W          = (const float*)d_in[5];
    const float* bias       = (const float*)d_in[6];
    float* out = (float*)d_out;

    static cudaStream_t s2 = nullptr;
    static cudaEvent_t evRoot, evChunk[NCHUNK], evDone;
    if (s2 == nullptr) {
        cudaStreamCreateWithFlags(&s2, cudaStreamNonBlocking);
        cudaEventCreateWithFlags(&evRoot, cudaEventDisableTiming);
        for (int i = 0; i < NCHUNK; i++)
            cudaEventCreateWithFlags(&evChunk[i], cudaEventDisableTiming);
        cudaEventCreateWithFlags(&evDone, cudaEventDisableTiming);
    }

    // fork side stream from capture stream
    cudaEventRecord(evRoot, 0);
    cudaStreamWaitEvent(s2, evRoot, 0);

    // transpose (needs only W) overlaps feat chunk 0
    transpose_kernel<<<TR_BLOCKS, 256, 0, s2>>>(W);

    for (int c = 0; c < NCHUNK; c++) {
        feat_kernel<<<FEATB_CH, 128>>>(ngram_ids, ngram_mask, ctx_ids, ctx_mask,
                                       embed, c * CHTOK);
        cudaEventRecord(evChunk[c], 0);
        cudaStreamWaitEvent(s2, evChunk[c], 0);
        gemm_kernel<<<GEMMB_CH, 192, 0, s2>>>(bias, out, c * GEMMB_CH);
    }

    // join side stream back into capture stream
    cudaEventRecord(evDone, s2);
    cudaStreamWaitEvent(0, evDone, 0);
}

// round 8
// speedup vs baseline: 3.6085x; 3.6085x over previous
#include <cuda_runtime.h>

#define BB 32
#define SS 128
#define KN 12
#define KC 10
#define KT 22
#define DD 200
#define D4 50
#define CC 45
#define CP 48
#define CP4 12
#define FF 1000
#define NTOK 4096

#define FEATB (NTOK / 2)                   // 2048 (2 tokens/block)
#define TR_ELEMS (FF * CP)                 // 48000
#define TR_BLOCKS ((TR_ELEMS + 127) / 128) // 375

#define GT 16                              // tokens per gemm tile
#define AR (GT + 4)                        // 20 staged A rows (halo)
#define APAD 51                            // shA pitch in float4
#define GEMMB (NTOK / GT)                  // 256

__device__ float g_feat[NTOK * DD];        // [tok, D]
__device__ float g_Wt[FF * CP];            // [k, 48] transposed+padded

// ---------------------------------------------------------------------------
// Kernel 1: masked gather+mean (2 tokens/block, reg-capped, ballot-compacted)
//           + W transpose appended to the same grid (R4-proven).
// ---------------------------------------------------------------------------
__global__ void __launch_bounds__(128, 16)
feat_tr_kernel(const int* __restrict__ ngram_ids,
               const int* __restrict__ ngram_mask,
               const int* __restrict__ ctx_ids,
               const int* __restrict__ ctx_mask,
               const float* __restrict__ embed,
               const float* __restrict__ W) {
    if (blockIdx.x >= FEATB) {
        int idx = (blockIdx.x - FEATB) * 128 + threadIdx.x;
        if (idx < TR_ELEMS) {
            int c = idx / FF;
            int k = idx - c * FF;
            g_Wt[k * CP + c] = (c < CC) ? W[c * FF + k] : 0.0f;
        }
        return;
    }

    const int half = threadIdx.x >> 6;
    const int lane = threadIdx.x & 63;
    const int tok  = blockIdx.x * 2 + half;

    __shared__ int s_act[2][24];
    __shared__ int s_cnt[2];

    if (lane < 32) {
        int m = 0, id = 0;
        if (lane < KN) {
            id = ngram_ids[tok * KN + lane];
            m  = ngram_mask[tok * KN + lane];
        } else if (lane < KT) {
            id = ctx_ids[tok * KC + lane - KN];
            m  = ctx_mask[tok * KC + lane - KN];
        }
        unsigned bal = __ballot_sync(0xffffffffu, m != 0);
        if (m) s_act[half][__popc(bal & ((1u << lane) - 1u))] = id;
        if (lane == 0) s_cnt[half] = __popc(bal);
    }
    __syncthreads();

    if (lane >= D4) return;

    const int n = s_cnt[half];
    const int* act = s_act[half];
    const float4* e4 = (const float4*)embed;

    float ax = 0.f, ay = 0.f, az = 0.f, aw = 0.f;
    int j = 0;
    for (; j + 4 <= n; j += 4) {
        float4 a = e4[(long long)act[j + 0] * D4 + lane];
        float4 b = e4[(long long)act[j + 1] * D4 + lane];
        float4 c = e4[(long long)act[j + 2] * D4 + lane];
        float4 d = e4[(long long)act[j + 3] * D4 + lane];
        ax += (a.x + b.x) + (c.x + d.x);
        ay += (a.y + b.y) + (c.y + d.y);
        az += (a.z + b.z) + (c.z + d.z);
        aw += (a.w + b.w) + (c.w + d.w);
    }
    for (; j < n; j++) {
        float4 a = e4[(long long)act[j] * D4 + lane];
        ax += a.x; ay += a.y; az += a.z; aw += a.w;
    }

    float inv = 1.0f / (float)(n > 0 ? n : 1);
    float4 r; r.x = ax * inv; r.y = ay * inv; r.z = az * inv; r.w = aw * inv;
    ((float4*)g_feat)[tok * D4 + lane] = r;
}

// ---------------------------------------------------------------------------
// Kernel 2: window-fused GEMM. Block = 16 tokens x 48 c, 192 threads.
// A (20 rows incl halo) staged ONCE; accumulate over w=0..4; B chunk per
// (w,h) staged float4-coalesced from g_Wt; writes out + bias directly.
// No partials, no reduce kernel.
// ---------------------------------------------------------------------------
__global__ void __launch_bounds__(192)
gemm_kernel(const float* __restrict__ bias,
            float* __restrict__ out) {
    __shared__ float4 shA[AR * APAD];        // 16320 B
    __shared__ float4 shB[100 * CP4];        // 19200 B

    const int tokBase = blockIdx.x * GT;
    const int b  = tokBase / SS;
    const int s0 = tokBase % SS;

    const int tid = threadIdx.x;
    const int tg = tid & 15;
    const int cg = tid >> 4;                 // 0..11

    const float4* gf4 = (const float4*)g_feat;
    for (int i = tid; i < AR * D4; i += 192) {
        int r  = i / D4;
        int dv = i - r * D4;
        int s  = s0 - 2 + r;
        float4 v = make_float4(0.f, 0.f, 0.f, 0.f);
        if (s >= 0 && s < SS) v = gf4[(b * SS + s) * D4 + dv];
        shA[r * APAD + dv] = v;
    }

    float acc0 = 0.f, acc1 = 0.f, acc2 = 0.f, acc3 = 0.f;
    const float4* Wt4 = (const float4*)g_Wt;

    #pragma unroll
    for (int w = 0; w < 5; w++) {
        #pragma unroll
        for (int h = 0; h < 2; h++) {
            __syncthreads();
            for (int i = tid; i < 100 * CP4; i += 192)
                shB[i] = Wt4[(w * DD + h * 100) * CP4 + i];
            __syncthreads();

            const float4* aRow = &shA[(tg + w) * APAD + h * 25];
            #pragma unroll
            for (int dq = 0; dq < 25; dq++) {
                float4 a  = aRow[dq];
                float4 b0 = shB[(dq * 4 + 0) * CP4 + cg];
                float4 b1 = shB[(dq * 4 + 1) * CP4 + cg];
                float4 b2 = shB[(dq * 4 + 2) * CP4 + cg];
                float4 b3 = shB[(dq * 4 + 3) * CP4 + cg];
                acc0 = fmaf(a.x, b0.x, acc0); acc1 = fmaf(a.x, b0.y, acc1);
                acc2 = fmaf(a.x, b0.z, acc2); acc3 = fmaf(a.x, b0.w, acc3);
                acc0 = fmaf(a.y, b1.x, acc0); acc1 = fmaf(a.y, b1.y, acc1);
                acc2 = fmaf(a.y, b1.z, acc2); acc3 = fmaf(a.y, b1.w, acc3);
                acc0 = fmaf(a.z, b2.x, acc0); acc1 = fmaf(a.z, b2.y, acc1);
                acc2 = fmaf(a.z, b2.z, acc2); acc3 = fmaf(a.z, b2.w, acc3);
                acc0 = fmaf(a.w, b3.x, acc0); acc1 = fmaf(a.w, b3.y, acc1);
                acc2 = fmaf(a.w, b3.z, acc2); acc3 = fmaf(a.w, b3.w, acc3);
            }
        }
    }

    const int c0 = cg * 4;
    float* o = out + (long long)(tokBase + tg) * CC;
    o[c0] = acc0 + bias[c0];
    if (c0 + 1 < CC) o[c0 + 1] = acc1 + bias[c0 + 1];
    if (c0 + 2 < CC) o[c0 + 2] = acc2 + bias[c0 + 2];
    if (c0 + 3 < CC) o[c0 + 3] = acc3 + bias[c0 + 3];
}

// ---------------------------------------------------------------------------
extern "C" void kernel_launch(void* const* d_in, const int* in_sizes, int n_in,
                              void* d_out, int out_size) {
    const int*   ngram_ids  = (const int*)d_in[0];
    const int*   ngram_mask = (const int*)d_in[1];
    const int*   ctx_ids    = (const int*)d_in[2];
    const int*   ctx_mask   = (const int*)d_in[3];
    const float* embed      = (const float*)d_in[4];
    const float* W          = (const float*)d_in[5];
    const float* bias       = (const float*)d_in[6];
    float* out = (float*)d_out;

    feat_tr_kernel<<<FEATB + TR_BLOCKS, 128>>>(
        ngram_ids, ngram_mask, ctx_ids, ctx_mask, embed, W);
    gemm_kernel<<<GEMMB, 192>>>(bias, out);
}

// round 9
// speedup vs baseline: 4.2023x; 1.1646x over previous
#include <cuda_runtime.h>

#define BB 32
#define SS 128
#define KN 12
#define KC 10
#define KT 22
#define DD 200
#define D4 50
#define CC 45
#define CP 48
#define CP4 12
#define FF 1000
#define NTOK 4096

#define FEATB (NTOK / 2)                   // 2048 (2 tokens/block)
#define TR_ELEMS (FF * CP)                 // 48000
#define TR_BLOCKS ((TR_ELEMS + 127) / 128) // 375

#define GT 32                              // tokens per gemm tile
#define NTILES (NTOK / GT)                 // 128
#define GEMMB (NTILES * 5)                 // 640
#define APAD 51                            // shA pitch in float4 (204 floats)

__device__ float g_feat[NTOK * DD];        // [tok, D]
__device__ float g_Wt[FF * CP];            // [k, 48] transposed+padded
__device__ float g_part[5 * NTOK * CP];    // [w, tok, 48]
__device__ int   g_cnt[NTILES];            // zero-init; reset by reducer

// ---------------------------------------------------------------------------
// Kernel 1 (R4-proven, unchanged): masked gather+mean, 2 tokens/block,
// ballot-compacted ids, reg-capped; W transpose appended to the grid.
// ---------------------------------------------------------------------------
__global__ void __launch_bounds__(128, 16)
feat_tr_kernel(const int* __restrict__ ngram_ids,
               const int* __restrict__ ngram_mask,
               const int* __restrict__ ctx_ids,
               const int* __restrict__ ctx_mask,
               const float* __restrict__ embed,
               const float* __restrict__ W) {
    if (blockIdx.x >= FEATB) {
        int idx = (blockIdx.x - FEATB) * 128 + threadIdx.x;
        if (idx < TR_ELEMS) {
            int c = idx / FF;
            int k = idx - c * FF;
            g_Wt[k * CP + c] = (c < CC) ? W[c * FF + k] : 0.0f;
        }
        return;
    }

    const int half = threadIdx.x >> 6;
    const int lane = threadIdx.x & 63;
    const int tok  = blockIdx.x * 2 + half;

    __shared__ int s_act[2][24];
    __shared__ int s_cnt[2];

    if (lane < 32) {
        int m = 0, id = 0;
        if (lane < KN) {
            id = ngram_ids[tok * KN + lane];
            m  = ngram_mask[tok * KN + lane];
        } else if (lane < KT) {
            id = ctx_ids[tok * KC + lane - KN];
            m  = ctx_mask[tok * KC + lane - KN];
        }
        unsigned bal = __ballot_sync(0xffffffffu, m != 0);
        if (m) s_act[half][__popc(bal & ((1u << lane) - 1u))] = id;
        if (lane == 0) s_cnt[half] = __popc(bal);
    }
    __syncthreads();

    if (lane >= D4) return;

    const int n = s_cnt[half];
    const int* act = s_act[half];
    const float4* e4 = (const float4*)embed;

    float ax = 0.f, ay = 0.f, az = 0.f, aw = 0.f;
    int j = 0;
    for (; j + 4 <= n; j += 4) {
        float4 a = e4[(long long)act[j + 0] * D4 + lane];
        float4 b = e4[(long long)act[j + 1] * D4 + lane];
        float4 c = e4[(long long)act[j + 2] * D4 + lane];
        float4 d = e4[(long long)act[j + 3] * D4 + lane];
        ax += (a.x + b.x) + (c.x + d.x);
        ay += (a.y + b.y) + (c.y + d.y);
        az += (a.z + b.z) + (c.z + d.z);
        aw += (a.w + b.w) + (c.w + d.w);
    }
    for (; j < n; j++) {
        float4 a = e4[(long long)act[j] * D4 + lane];
        ax += a.x; ay += a.y; az += a.z; aw += a.w;
    }

    float inv = 1.0f / (float)(n > 0 ? n : 1);
    float4 r; r.x = ax * inv; r.y = ay * inv; r.z = az * inv; r.w = aw * inv;
    ((float4*)g_feat)[tok * D4 + lane] = r;
}

// ---------------------------------------------------------------------------
// Kernel 2: per-window partial GEMM, 2 tokens x 4 c per thread, fused
// last-block reduction. Grid 640 = 128 tiles x 5 w, 192 threads.
// ---------------------------------------------------------------------------
__global__ void __launch_bounds__(192)
gemm_kernel(const float* __restrict__ bias,
            float* __restrict__ out) {
    __shared__ float4 shA[GT * APAD];        // 26112 B
    __shared__ float4 shB[100 * CP4];        // 19200 B
    __shared__ int s_last;

    const int q = blockIdx.x;
    const int tile = q / 5;
    const int w = q - tile * 5;
    const int tokBase = tile * GT;
    const int b  = tokBase / SS;
    const int s0 = tokBase % SS;

    const int tid = threadIdx.x;
    const int tg = tid & 15;                 // tokens tg and tg+16
    const int cg = tid >> 4;                 // 0..11

    // stage A rows s0+w-2 .. s0+w+29 (zero halo)
    const float4* gf4 = (const float4*)g_feat;
    for (int i = tid; i < GT * D4; i += 192) {
        int r  = i / D4;
        int dv = i - r * D4;
        int s  = s0 + w - 2 + r;
        float4 v = make_float4(0.f, 0.f, 0.f, 0.f);
        if (s >= 0 && s < SS) v = gf4[(b * SS + s) * D4 + dv];
        shA[r * APAD + dv] = v;
    }

    float p00 = 0.f, p01 = 0.f, p02 = 0.f, p03 = 0.f;   // token tg
    float p10 = 0.f, p11 = 0.f, p12 = 0.f, p13 = 0.f;   // token tg+16
    const float4* Wt4 = (const float4*)g_Wt;

    #pragma unroll
    for (int h = 0; h < 2; h++) {
        __syncthreads();
        for (int i = tid; i < 100 * CP4; i += 192)
            shB[i] = Wt4[(w * DD + h * 100) * CP4 + i];
        __syncthreads();

        const float4* aRow0 = &shA[tg * APAD + h * 25];
        const float4* aRow1 = &shA[(tg + 16) * APAD + h * 25];
        #pragma unroll
        for (int dq = 0; dq < 25; dq++) {
            float4 a0 = aRow0[dq];
            float4 a1 = aRow1[dq];
            float4 b0 = shB[(dq * 4 + 0) * CP4 + cg];
            float4 b1 = shB[(dq * 4 + 1) * CP4 + cg];
            float4 b2 = shB[(dq * 4 + 2) * CP4 + cg];
            float4 b3 = shB[(dq * 4 + 3) * CP4 + cg];
            p00 = fmaf(a0.x, b0.x, p00); p01 = fmaf(a0.x, b0.y, p01);
            p02 = fmaf(a0.x, b0.z, p02); p03 = fmaf(a0.x, b0.w, p03);
            p10 = fmaf(a1.x, b0.x, p10); p11 = fmaf(a1.x, b0.y, p11);
            p12 = fmaf(a1.x, b0.z, p12); p13 = fmaf(a1.x, b0.w, p13);
            p00 = fmaf(a0.y, b1.x, p00); p01 = fmaf(a0.y, b1.y, p01);
            p02 = fmaf(a0.y, b1.z, p02); p03 = fmaf(a0.y, b1.w, p03);
            p10 = fmaf(a1.y, b1.x, p10); p11 = fmaf(a1.y, b1.y, p11);
            p12 = fmaf(a1.y, b1.z, p12); p13 = fmaf(a1.y, b1.w, p13);
            p00 = fmaf(a0.z, b2.x, p00); p01 = fmaf(a0.z, b2.y, p01);
            p02 = fmaf(a0.z, b2.z, p02); p03 = fmaf(a0.z, b2.w, p03);
            p10 = fmaf(a1.z, b2.x, p10); p11 = fmaf(a1.z, b2.y, p11);
            p12 = fmaf(a1.z, b2.z, p12); p13 = fmaf(a1.z, b2.w, p13);
            p00 = fmaf(a0.w, b3.x, p00); p01 = fmaf(a0.w, b3.y, p01);
            p02 = fmaf(a0.w, b3.z, p02); p03 = fmaf(a0.w, b3.w, p03);
            p10 = fmaf(a1.w, b3.x, p10); p11 = fmaf(a1.w, b3.y, p11);
            p12 = fmaf(a1.w, b3.z, p12); p13 = fmaf(a1.w, b3.w, p13);
        }
    }

    // write partials
    float4* part4 = (float4*)g_part;
    float4 v0; v0.x = p00; v0.y = p01; v0.z = p02; v0.w = p03;
    float4 v1; v1.x = p10; v1.y = p11; v1.z = p12; v1.w = p13;
    part4[((long long)w * NTOK + tokBase + tg) * CP4 + cg] = v0;
    part4[((long long)w * NTOK + tokBase + tg + 16) * CP4 + cg] = v1;

    // last-block-of-tile reduction (fixed w-order sum -> deterministic)
    __threadfence();
    __syncthreads();
    if (tid == 0) {
        int old = atomicAdd(&g_cnt[tile], 1);
        s_last = (old == 4);
    }
    __syncthreads();
    if (!s_last) return;
    __threadfence();

    #pragma unroll
    for (int half = 0; half < 2; half++) {
        int t = tg + half * 16;
        int tok = tokBase + t;
        float4 s = make_float4(0.f, 0.f, 0.f, 0.f);
        #pragma unroll
        for (int w2 = 0; w2 < 5; w2++) {
            float4 p = part4[((long long)w2 * NTOK + tok) * CP4 + cg];
            s.x += p.x; s.y += p.y; s.z += p.z; s.w += p.w;
        }
        int c0 = cg * 4;
        float* o = out + (long long)tok * CC;
        o[c0] = s.x + bias[c0];
        if (c0 + 1 < CC) o[c0 + 1] = s.y + bias[c0 + 1];
        if (c0 + 2 < CC) o[c0 + 2] = s.z + bias[c0 + 2];
        if (c0 + 3 < CC) o[c0 + 3] = s.w + bias[c0 + 3];
    }
    if (tid == 0) g_cnt[tile] = 0;           // reset for next graph replay
}

// ---------------------------------------------------------------------------
extern "C" void kernel_launch(void* const* d_in, const int* in_sizes, int n_in,
                              void* d_out, int out_size) {
    const int*   ngram_ids  = (const int*)d_in[0];
    const int*   ngram_mask = (const int*)d_in[1];
    const int*   ctx_ids    = (const int*)d_in[2];
    const int*   ctx_mask   = (const int*)d_in[3];
    const float* embed      = (const float*)d_in[4];
    const float* W          = (const float*)d_in[5];
    const float* bias       = (const float*)d_in[6];
    float* out = (float*)d_out;

    feat_tr_kernel<<<FEATB + TR_BLOCKS, 128>>>(
        ngram_ids, ngram_mask, ctx_ids, ctx_mask, embed, W);
    gemm_kernel<<<GEMMB, 192>>>(bias, out);
}